// round 5
// baseline (speedup 1.0000x reference)
#include <cuda_runtime.h>
#include <cstdint>

#define BZ 8
#define NF 10000
#define DD 16
#define HH 512
#define WW 512
#define NPIX (BZ * HH * WW)
#define HWPIX (HH * WW)

#define TPB 256
#define PIX_PER_BLOCK (TPB / 4)   // 4 threads per pixel

__global__ __launch_bounds__(TPB) void renderer_kernel(
    const float4* __restrict__ attrs,     // records of 12 float4, stride 192 B
    const float*  __restrict__ baryw,     // [BZ,H,W,3]
    const int*    __restrict__ tri,       // [BZ,H,W]
    float*        __restrict__ out)       // [BZ, D+1, H, W]
{
    const int t   = blockIdx.x * TPB + threadIdx.x;
    const int p   = t >> 2;               // pixel
    const int j   = t & 3;                // channel quad (channels 4j..4j+3)

    int tr = tri[p];
    bool fg = (tr >= 0);
    int ti = fg ? tr : 0;

    // 4 lanes of the same pixel read the same 3 floats -> coalescer merges.
    float w0 = baryw[p * 3 + 0];
    float w1 = baryw[p * 3 + 1];
    float w2 = baryw[p * 3 + 2];
    float m = fg ? 1.0f : 0.0f;
    w0 *= m; w1 *= m; w2 *= m;

    // Gather: lane j loads float4 j of each vertex. Per LDG.128 instruction the
    // warp touches 8 records x one 64B-aligned chunk = 8 L1 wavefronts.
    const float4* rec = attrs + (size_t)ti * 12;
    float4 a0 = rec[j];        // vertex 0
    float4 a1 = rec[4 + j];    // vertex 1
    float4 a2 = rec[8 + j];    // vertex 2

    float r0 = fmaf(w0, a0.x, fmaf(w1, a1.x, w2 * a2.x));
    float r1 = fmaf(w0, a0.y, fmaf(w1, a1.y, w2 * a2.y));
    float r2 = fmaf(w0, a0.z, fmaf(w1, a1.z, w2 * a2.z));
    float r3 = fmaf(w0, a0.w, fmaf(w1, a1.w, w2 * a2.w));

    int n  = p / HWPIX;
    int hw = p - n * HWPIX;
    float* obase = out + (size_t)n * (DD + 1) * HWPIX + hw;

    // Channel-strided stores: for each instruction, lanes with the same j form
    // 8 consecutive pixels -> one 32B sector per channel-group per line.
    obase[(size_t)(4 * j + 0) * HWPIX] = r0;
    obase[(size_t)(4 * j + 1) * HWPIX] = r1;
    obase[(size_t)(4 * j + 2) * HWPIX] = r2;
    obase[(size_t)(4 * j + 3) * HWPIX] = r3;
    if (j == 0)
        obase[(size_t)DD * HWPIX] = m;   // visibility channel
}

extern "C" void kernel_launch(void* const* d_in, const int* in_sizes, int n_in,
                              void* d_out, int out_size) {
    const float4* attrs = (const float4*)d_in[0];
    const float*  baryw = (const float*)d_in[1];
    const int*    tri   = (const int*)d_in[2];
    float*        out   = (float*)d_out;

    int blocks = NPIX / PIX_PER_BLOCK;   // 32768, exact
    renderer_kernel<<<blocks, TPB>>>(attrs, baryw, tri, out);
}